// round 3
// baseline (speedup 1.0000x reference)
#include <cuda_runtime.h>
#include <cuda_bf16.h>
#include <math.h>

#define Bn   128
#define Tn   200
#define Vn   50257
#define Hn   256
#define En   128
#define OOV  50
#define H2   512           // 2H
#define XD   640           // E + 2H
#define PV   (Vn + OOV)    // 50307

// ---------------- scratch (static device memory; no allocs) ----------------
__device__ float g_score[(size_t)Bn * Vn];   // score_g  (B, V)
__device__ float g_scorec[Bn * Tn];          // score_c  (B, T)
__device__ float g_max[Bn];
__device__ float g_invsum[Bn];

// ---------------------------------------------------------------------------
// Kernel A: GRU cell.  One block per batch row, 256 threads (= H).
// gru_in = [selective_read(512), emb[dec](128)]; handles step==0 path.
// ---------------------------------------------------------------------------
__global__ __launch_bounds__(256) void gru_kernel(
    const int* __restrict__ dec_in, const float* __restrict__ enc,
    const int* __restrict__ step,
    const float* __restrict__ prev_state, const float* __restrict__ sel,
    const float* __restrict__ emb,
    const float* __restrict__ W_ih, const float* __restrict__ W_hh,
    const float* __restrict__ b_ih, const float* __restrict__ b_hh,
    const float* __restrict__ Wi_w, const float* __restrict__ Wi_b,
    float* __restrict__ dh_out)
{
    __shared__ __align__(16) float xs[XD];
    __shared__ __align__(16) float hs[Hn];
    __shared__ __align__(16) float es[H2];

    const int b   = blockIdx.x;
    const int tid = threadIdx.x;
    const int stepv = step ? step[0] : 1;
    const int dec = dec_in[b];

    if (stepv != 0) {
        xs[tid]       = sel[b * H2 + tid];
        xs[tid + 256] = sel[b * H2 + tid + 256];
    } else {
        xs[tid] = 0.f; xs[tid + 256] = 0.f;
    }
    if (tid < En) xs[H2 + tid] = emb[(size_t)dec * En + tid];

    if (stepv != 0) {
        hs[tid] = prev_state[b * Hn + tid];
    } else {
        const float* el = enc + (size_t)b * Tn * H2 + (size_t)(Tn - 1) * H2;
        es[tid]       = el[tid];
        es[tid + 256] = el[tid + 256];
        __syncthreads();
        float acc = Wi_b[tid];
        const float4* wr = (const float4*)(Wi_w + (size_t)tid * H2);
        const float4* ev = (const float4*)es;
        #pragma unroll 8
        for (int k = 0; k < H2 / 4; k++) {
            float4 w = wr[k], e = ev[k];
            acc += w.x * e.x + w.y * e.y + w.z * e.z + w.w * e.w;
        }
        hs[tid] = acc;
    }
    __syncthreads();

    const int j = tid;
    float gir = b_ih[j], giz = b_ih[Hn + j], gin = b_ih[2 * Hn + j];
    {
        const float4* x4 = (const float4*)xs;
        const float4* r0 = (const float4*)(W_ih + (size_t)j * XD);
        const float4* r1 = (const float4*)(W_ih + (size_t)(Hn + j) * XD);
        const float4* r2 = (const float4*)(W_ih + (size_t)(2 * Hn + j) * XD);
        float a0 = 0.f, a1 = 0.f, a2 = 0.f;
        #pragma unroll 8
        for (int k = 0; k < XD / 4; k++) {
            float4 x = x4[k];
            float4 w0 = r0[k], w1 = r1[k], w2 = r2[k];
            a0 += w0.x * x.x + w0.y * x.y + w0.z * x.z + w0.w * x.w;
            a1 += w1.x * x.x + w1.y * x.y + w1.z * x.z + w1.w * x.w;
            a2 += w2.x * x.x + w2.y * x.y + w2.z * x.z + w2.w * x.w;
        }
        gir += a0; giz += a1; gin += a2;
    }
    float ghr = b_hh[j], ghz = b_hh[Hn + j], ghn = b_hh[2 * Hn + j];
    {
        const float4* h4 = (const float4*)hs;
        const float4* r0 = (const float4*)(W_hh + (size_t)j * Hn);
        const float4* r1 = (const float4*)(W_hh + (size_t)(Hn + j) * Hn);
        const float4* r2 = (const float4*)(W_hh + (size_t)(2 * Hn + j) * Hn);
        float a0 = 0.f, a1 = 0.f, a2 = 0.f;
        #pragma unroll 8
        for (int k = 0; k < Hn / 4; k++) {
            float4 x = h4[k];
            float4 w0 = r0[k], w1 = r1[k], w2 = r2[k];
            a0 += w0.x * x.x + w0.y * x.y + w0.z * x.z + w0.w * x.w;
            a1 += w1.x * x.x + w1.y * x.y + w1.z * x.z + w1.w * x.w;
            a2 += w2.x * x.x + w2.y * x.y + w2.z * x.z + w2.w * x.w;
        }
        ghr += a0; ghz += a1; ghn += a2;
    }
    float r = 1.f / (1.f + expf(-(gir + ghr)));
    float z = 1.f / (1.f + expf(-(giz + ghz)));
    float n = tanhf(gin + r * ghn);
    dh_out[b * Hn + j] = (1.f - z) * n + z * hs[j];
}

// ---------------------------------------------------------------------------
// Kernel B: score_g = dh(128x256) @ Wg^T(256xV) + Wg_b.
// Tiled SGEMM: BM=128 (all batches -> Wg read once from DRAM), BN=64, BK=32.
// 256 threads, 8x4 micro-tile per thread.
// ---------------------------------------------------------------------------
__global__ __launch_bounds__(256) void scoreg_kernel(
    const float* __restrict__ dh,
    const float* __restrict__ Wg, const float* __restrict__ Wgb)
{
    __shared__ float As[32 * 129];  // [k][b], padded
    __shared__ float Bs[32 * 65];   // [k][v], padded

    const int tid  = threadIdx.x;
    const int v0   = blockIdx.x * 64;
    const int row0 = (tid >> 4) * 8;   // batch base
    const int col0 = (tid & 15) * 4;   // v base within tile

    float acc[8][4];
    #pragma unroll
    for (int r = 0; r < 8; r++)
        #pragma unroll
        for (int c = 0; c < 4; c++) acc[r][c] = 0.f;

    for (int kt = 0; kt < 256; kt += 32) {
        for (int i = tid; i < 128 * 32; i += 256) {
            int bb = i >> 5, k = i & 31;
            As[k * 129 + bb] = dh[bb * 256 + kt + k];
        }
        for (int i = tid; i < 64 * 32; i += 256) {
            int v = i >> 5, k = i & 31;
            int vg = v0 + v;
            Bs[k * 65 + v] = (vg < Vn) ? Wg[(size_t)vg * 256 + kt + k] : 0.f;
        }
        __syncthreads();
        #pragma unroll
        for (int k = 0; k < 32; k++) {
            float a[8], bv[4];
            #pragma unroll
            for (int r = 0; r < 8; r++) a[r] = As[k * 129 + row0 + r];
            #pragma unroll
            for (int c = 0; c < 4; c++) bv[c] = Bs[k * 65 + col0 + c];
            #pragma unroll
            for (int r = 0; r < 8; r++)
                #pragma unroll
                for (int c = 0; c < 4; c++) acc[r][c] += a[r] * bv[c];
        }
        __syncthreads();
    }
    #pragma unroll
    for (int c = 0; c < 4; c++) {
        int vg = v0 + col0 + c;
        if (vg < Vn) {
            float bias = Wgb[vg];
            #pragma unroll
            for (int r = 0; r < 8; r++)
                g_score[(size_t)(row0 + r) * Vn + vg] = acc[r][c] + bias;
        }
    }
}

// ---------------------------------------------------------------------------
// Kernel C: enc_proj = tanh(enc @ Wc^T + Wc_b); score_c = tanh(enc_proj . dh)
//           + mask. Fused: P tile kept in registers, dh contraction in-epilogue.
// Block = (b, t-tile of 50). 320 threads, 5x8 micro-tile, K=512 in BK=32.
// ---------------------------------------------------------------------------
__global__ __launch_bounds__(320, 2) void scorec_kernel(
    const float* __restrict__ enc, const int* __restrict__ encIdx,
    const float* __restrict__ Wc, const float* __restrict__ Wcb,
    const float* __restrict__ dh)
{
    __shared__ float dhs[256];
    __shared__ float Es[32 * 51];    // [k][t]
    __shared__ float Ws[32 * 257];   // [k][h]

    const int b   = blockIdx.y;
    const int t0  = blockIdx.x * 50;
    const int tid = threadIdx.x;
    const int it   = tid >> 5;       // 0..9  (t-group)
    const int lane = tid & 31;       // 0..31 (h-group) == warp lane
    const int tb = it * 5, hb = lane * 8;

    if (tid < 256) dhs[tid] = dh[b * 256 + tid];

    float acc[5][8];
    #pragma unroll
    for (int i = 0; i < 5; i++)
        #pragma unroll
        for (int j = 0; j < 8; j++) acc[i][j] = 0.f;

    const float* encb = enc + (size_t)b * Tn * H2;

    for (int kt = 0; kt < 512; kt += 32) {
        for (int i = tid; i < 50 * 32; i += 320) {
            int t = i >> 5, k = i & 31;
            Es[k * 51 + t] = encb[(size_t)(t0 + t) * 512 + kt + k];
        }
        for (int i = tid; i < 256 * 32; i += 320) {
            int h = i >> 5, k = i & 31;
            Ws[k * 257 + h] = Wc[(size_t)h * 512 + kt + k];
        }
        __syncthreads();
        #pragma unroll
        for (int k = 0; k < 32; k++) {
            float a[5], w[8];
            #pragma unroll
            for (int i = 0; i < 5; i++) a[i] = Es[k * 51 + tb + i];
            #pragma unroll
            for (int j = 0; j < 8; j++) w[j] = Ws[k * 257 + hb + j];
            #pragma unroll
            for (int i = 0; i < 5; i++)
                #pragma unroll
                for (int j = 0; j < 8; j++) acc[i][j] += a[i] * w[j];
        }
        __syncthreads();
    }

    float bias[8], dv[8];
    #pragma unroll
    for (int j = 0; j < 8; j++) { bias[j] = Wcb[hb + j]; dv[j] = dhs[hb + j]; }

    #pragma unroll
    for (int i = 0; i < 5; i++) {
        float s = 0.f;
        #pragma unroll
        for (int j = 0; j < 8; j++)
            s += tanhf(acc[i][j] + bias[j]) * dv[j];
        // warp reduce over the 32 h-groups (lanes)
        #pragma unroll
        for (int off = 16; off > 0; off >>= 1)
            s += __shfl_down_sync(0xffffffffu, s, off);
        if (lane == 0) {
            int t = t0 + tb + i;
            float sc = tanhf(s);
            if (encIdx[b * Tn + t] == 0) sc -= 10000.f;
            g_scorec[b * Tn + t] = sc;
        }
    }
}

// ---------------------------------------------------------------------------
// Kernel D: per-row softmax stats over concat[score_g(V), score_c(T)].
// ---------------------------------------------------------------------------
__global__ __launch_bounds__(256) void stats_kernel()
{
    __shared__ float red[256];
    const int b = blockIdx.x, tid = threadIdx.x;
    const int L = Vn + Tn;

    float m = -INFINITY;
    for (int i = tid; i < L; i += 256) {
        float v = (i < Vn) ? g_score[(size_t)b * Vn + i] : g_scorec[b * Tn + (i - Vn)];
        m = fmaxf(m, v);
    }
    red[tid] = m; __syncthreads();
    for (int s = 128; s > 0; s >>= 1) {
        if (tid < s) red[tid] = fmaxf(red[tid], red[tid + s]);
        __syncthreads();
    }
    float mx = red[0];
    __syncthreads();

    float sum = 0.f;
    for (int i = tid; i < L; i += 256) {
        float v = (i < Vn) ? g_score[(size_t)b * Vn + i] : g_scorec[b * Tn + (i - Vn)];
        sum += expf(v - mx);
    }
    red[tid] = sum; __syncthreads();
    for (int s = 128; s > 0; s >>= 1) {
        if (tid < s) red[tid] += red[tid + s];
        __syncthreads();
    }
    if (tid == 0) { g_max[b] = mx; g_invsum[b] = 1.f / red[0]; }
}

// ---------------------------------------------------------------------------
// Kernel E: prob_out base = [ prob_g (V) | 0.0001 (MAX_OOV) ].
// ---------------------------------------------------------------------------
__global__ __launch_bounds__(256) void probg_kernel(float* __restrict__ out)
{
    int idx = blockIdx.x * 256 + threadIdx.x;
    if (idx >= Bn * PV) return;
    int b = idx / PV, v = idx - b * PV;
    out[idx] = (v < Vn)
        ? expf(g_score[(size_t)b * Vn + v] - g_max[b]) * g_invsum[b]
        : 1e-4f;
}

// ---------------------------------------------------------------------------
// Kernel F: prob_c, scatter-add into prob_out, selective_read_new.
// One block per batch row.
// ---------------------------------------------------------------------------
__global__ __launch_bounds__(256) void final_kernel(
    const int* __restrict__ dec_in, const int* __restrict__ encIdx,
    const float* __restrict__ enc,
    float* __restrict__ prob_out, float* __restrict__ sel_out)
{
    __shared__ float pc[Tn];
    __shared__ float wt[Tn];
    __shared__ float norm;

    const int b = blockIdx.x, tid = threadIdx.x;
    const float mx = g_max[b], inv = g_invsum[b];
    const int dec = dec_in[b];

    if (tid < Tn) {
        float p = expf(g_scorec[b * Tn + tid] - mx) * inv;
        pc[tid] = p;
        wt[tid] = (encIdx[b * Tn + tid] == dec) ? 1.f : 0.f;
    }
    __syncthreads();
    if (tid == 0) {
        float t = 0.f;
        for (int i = 0; i < Tn; i++) t += wt[i];
        norm = (t > 1.f) ? 1.f / t : 1.f;
    }
    __syncthreads();
    float nf = norm;
    if (tid < Tn) {
        wt[tid] = wt[tid] * pc[tid] * nf;
        atomicAdd(&prob_out[(size_t)b * PV + encIdx[b * Tn + tid]], pc[tid]);
    }
    __syncthreads();

    const float* encb = enc + (size_t)b * Tn * H2;
    for (int e = tid; e < H2; e += 256) {
        float s = 0.f;
        #pragma unroll 4
        for (int t = 0; t < Tn; t++) s += wt[t] * encb[(size_t)t * H2 + e];
        sel_out[b * H2 + e] = s;
    }
}

// ---------------------------------------------------------------------------
extern "C" void kernel_launch(void* const* d_in, const int* in_sizes, int n_in,
                              void* d_out, int out_size)
{
    const int*   dec  = (const int*)d_in[0];
    const float* enc  = (const float*)d_in[1];
    const int*   eidx = (const int*)d_in[2];
    const float* prev = (const float*)d_in[3];
    const float* sel  = (const float*)d_in[4];
    const int si = (n_in >= 17) ? 1 : 0;          // is 'step' passed as input?
    const int* step = si ? (const int*)d_in[5] : nullptr;
    const float* emb = (const float*)d_in[5 + si];
    const float* Wih = (const float*)d_in[6 + si];
    const float* Whh = (const float*)d_in[7 + si];
    const float* bih = (const float*)d_in[8 + si];
    const float* bhh = (const float*)d_in[9 + si];
    const float* Wiw = (const float*)d_in[10 + si];
    const float* Wib = (const float*)d_in[11 + si];
    const float* Wgw = (const float*)d_in[12 + si];
    const float* Wgb = (const float*)d_in[13 + si];
    const float* Wcw = (const float*)d_in[14 + si];
    const float* Wcb = (const float*)d_in[15 + si];

    float* out    = (float*)d_out;
    float* prob   = out;                              // (B, 1, V+OOV)
    float* dh     = out + (size_t)Bn * PV;            // (B, H)
    float* selnew = dh + Bn * Hn;                     // (B, 1, 2H)

    gru_kernel<<<Bn, 256>>>(dec, enc, step, prev, sel, emb, Wih, Whh, bih, bhh,
                            Wiw, Wib, dh);
    scoreg_kernel<<<(Vn + 63) / 64, 256>>>(dh, Wgw, Wgb);
    dim3 gc(4, Bn);
    scorec_kernel<<<gc, 320>>>(enc, eidx, Wcw, Wcb, dh);
    stats_kernel<<<Bn, 256>>>();
    probg_kernel<<<(Bn * PV + 255) / 256, 256>>>(prob);
    final_kernel<<<Bn, 256>>>(dec, eidx, enc, prob, selnew);
}